// round 1
// baseline (speedup 1.0000x reference)
#include <cuda_runtime.h>
#include <math.h>

#define NTOK 16384
#define DM   1024
#define DFFN 4096
#define NE   8
#define TOPK 2

#define BM 128
#define BN 128
#define BK 8
#define TM 8
#define TN 8

// ---- device scratch (allocation-free: static globals) ----
__device__ int   g_cnt[NE];
__device__ int   g_off[NE];
__device__ int   g_tok[NE * NTOK];
__device__ float g_wt [NE * NTOK];
// compact hidden activations: sum of per-expert rows = NTOK*TOPK
__device__ float g_h[(size_t)NTOK * TOPK * DFFN];   // 512 MB

// ---------------------------------------------------------------------------
// zero output + counters
// ---------------------------------------------------------------------------
__global__ void zero_kernel(float* __restrict__ out) {
    size_t i = (size_t)blockIdx.x * blockDim.x + threadIdx.x;
    const size_t tot4 = (size_t)NTOK * DM / 4;
    if (i < tot4) ((float4*)out)[i] = make_float4(0.f, 0.f, 0.f, 0.f);
    if (i < NE) g_cnt[i] = 0;
}

// ---------------------------------------------------------------------------
// gating: one warp per token. logits = x @ gate_W + gate_b, exact top-2,
// softmax over the 2 selected, route into per-expert lists.
// ---------------------------------------------------------------------------
__global__ __launch_bounds__(256) void gating_kernel(
    const float* __restrict__ x, const float* __restrict__ gW,
    const float* __restrict__ gb, float* __restrict__ out_topi,
    int write_topi) {
    int warp = (int)((blockIdx.x * blockDim.x + threadIdx.x) >> 5);
    int lane = threadIdx.x & 31;
    if (warp >= NTOK) return;
    const float* xr = x + (size_t)warp * DM;
    float acc[NE];
#pragma unroll
    for (int e = 0; e < NE; e++) acc[e] = 0.f;
    for (int d = lane; d < DM; d += 32) {
        float xv = xr[d];
        const float4* w4 = (const float4*)(gW + d * NE);
        float4 wa = w4[0], wb = w4[1];
        acc[0] += xv * wa.x; acc[1] += xv * wa.y;
        acc[2] += xv * wa.z; acc[3] += xv * wa.w;
        acc[4] += xv * wb.x; acc[5] += xv * wb.y;
        acc[6] += xv * wb.z; acc[7] += xv * wb.w;
    }
#pragma unroll
    for (int e = 0; e < NE; e++)
#pragma unroll
        for (int o = 16; o > 0; o >>= 1)
            acc[e] += __shfl_xor_sync(0xffffffffu, acc[e], o);

    if (lane == 0) {
        float v0 = -1e30f, v1 = -1e30f; int i0 = 0, i1 = 0;
#pragma unroll
        for (int e = 0; e < NE; e++) {
            float l = acc[e] + gb[e];
            if (l > v0)      { v1 = v0; i1 = i0; v0 = l; i0 = e; }
            else if (l > v1) { v1 = l;  i1 = e; }
        }
        // softmax over [v0, v1], v0 is max (matches jax top_k descending order)
        float e1 = expf(v1 - v0);
        float s  = 1.f + e1;
        float w0 = 1.f / s, w1 = e1 / s;
        int p0 = atomicAdd(&g_cnt[i0], 1);
        g_tok[i0 * NTOK + p0] = warp; g_wt[i0 * NTOK + p0] = w0;
        int p1 = atomicAdd(&g_cnt[i1], 1);
        g_tok[i1 * NTOK + p1] = warp; g_wt[i1 * NTOK + p1] = w1;
        if (write_topi) {
            out_topi[warp * 2 + 0] = (float)i0;
            out_topi[warp * 2 + 1] = (float)i1;
        }
    }
}

__global__ void prefix_kernel() {
    int s = 0;
    for (int e = 0; e < NE; e++) { g_off[e] = s; s += g_cnt[e]; }
}

// ---------------------------------------------------------------------------
// GEMM1: h[off[e]+r, :] = gelu(x[tok_r] @ W1[e] + b1[e]),  K = DM
// 128x128 block, 8x8 per thread, BK=8, fp32
// ---------------------------------------------------------------------------
__global__ __launch_bounds__(256) void gemm1_kernel(
    const float* __restrict__ x, const float* __restrict__ W1,
    const float* __restrict__ b1) {
    int e = blockIdx.z;
    int rows = g_cnt[e];
    int row0 = blockIdx.y * BM;
    if (row0 >= rows) return;
    int col0 = blockIdx.x * BN;
    const float* W    = W1 + (size_t)e * DM * DFFN;
    const float* bias = b1 + (size_t)e * DFFN;

    __shared__ float As[BK][BM];
    __shared__ float Bs[BK][BN];
    int tid = threadIdx.x;
    int tx = tid & 15, ty = tid >> 4;
    float acc[TM][TN];
#pragma unroll
    for (int i = 0; i < TM; i++)
#pragma unroll
        for (int j = 0; j < TN; j++) acc[i][j] = 0.f;

    int a_r = tid >> 1, a_k = (tid & 1) * 4;
    int b_k = tid >> 5, b_c = (tid & 31) * 4;
    const float* xrow = 0;
    {
        int gr = row0 + a_r;
        if (gr < rows) xrow = x + (size_t)g_tok[e * NTOK + gr] * DM;
    }

    for (int k0 = 0; k0 < DM; k0 += BK) {
        float4 av = xrow ? *(const float4*)(xrow + k0 + a_k)
                         : make_float4(0.f, 0.f, 0.f, 0.f);
        As[a_k + 0][a_r] = av.x; As[a_k + 1][a_r] = av.y;
        As[a_k + 2][a_r] = av.z; As[a_k + 3][a_r] = av.w;
        *(float4*)&Bs[b_k][b_c] =
            *(const float4*)(W + (size_t)(k0 + b_k) * DFFN + col0 + b_c);
        __syncthreads();
#pragma unroll
        for (int k = 0; k < BK; k++) {
            float ar[TM], br[TN];
            *(float4*)(ar)     = *(const float4*)&As[k][ty * TM];
            *(float4*)(ar + 4) = *(const float4*)&As[k][ty * TM + 4];
            *(float4*)(br)     = *(const float4*)&Bs[k][tx * TN];
            *(float4*)(br + 4) = *(const float4*)&Bs[k][tx * TN + 4];
#pragma unroll
            for (int i = 0; i < TM; i++)
#pragma unroll
                for (int j = 0; j < TN; j++)
                    acc[i][j] += ar[i] * br[j];
        }
        __syncthreads();
    }

    int hbase = g_off[e];
#pragma unroll
    for (int i = 0; i < TM; i++) {
        int r = row0 + ty * TM + i;
        if (r < rows) {
            float* hrow = g_h + (size_t)(hbase + r) * DFFN + col0 + tx * TN;
#pragma unroll
            for (int j = 0; j < TN; j++) {
                float v = acc[i][j] + bias[col0 + tx * TN + j];
                hrow[j] = 0.5f * v * (1.f + erff(v * 0.70710678118654752f));
            }
        }
    }
}

// ---------------------------------------------------------------------------
// GEMM2: out[tok_r, :] += wt_r * (h[off[e]+r, :] @ W2[e] + b2[e]),  K = DFFN
// ---------------------------------------------------------------------------
__global__ __launch_bounds__(256) void gemm2_kernel(
    const float* __restrict__ W2, const float* __restrict__ b2,
    float* __restrict__ out) {
    int e = blockIdx.z;
    int rows = g_cnt[e];
    int row0 = blockIdx.y * BM;
    if (row0 >= rows) return;
    int col0 = blockIdx.x * BN;
    const float* W    = W2 + (size_t)e * DFFN * DM;
    const float* bias = b2 + (size_t)e * DM;
    int hbase = g_off[e];

    __shared__ float As[BK][BM];
    __shared__ float Bs[BK][BN];
    int tid = threadIdx.x;
    int tx = tid & 15, ty = tid >> 4;
    float acc[TM][TN];
#pragma unroll
    for (int i = 0; i < TM; i++)
#pragma unroll
        for (int j = 0; j < TN; j++) acc[i][j] = 0.f;

    int a_r = tid >> 1, a_k = (tid & 1) * 4;
    int b_k = tid >> 5, b_c = (tid & 31) * 4;
    const float* hrow_ld = 0;
    {
        int gr = row0 + a_r;
        if (gr < rows) hrow_ld = g_h + (size_t)(hbase + gr) * DFFN;
    }

    for (int k0 = 0; k0 < DFFN; k0 += BK) {
        float4 av = hrow_ld ? *(const float4*)(hrow_ld + k0 + a_k)
                            : make_float4(0.f, 0.f, 0.f, 0.f);
        As[a_k + 0][a_r] = av.x; As[a_k + 1][a_r] = av.y;
        As[a_k + 2][a_r] = av.z; As[a_k + 3][a_r] = av.w;
        *(float4*)&Bs[b_k][b_c] =
            *(const float4*)(W + (size_t)(k0 + b_k) * DM + col0 + b_c);
        __syncthreads();
#pragma unroll
        for (int k = 0; k < BK; k++) {
            float ar[TM], br[TN];
            *(float4*)(ar)     = *(const float4*)&As[k][ty * TM];
            *(float4*)(ar + 4) = *(const float4*)&As[k][ty * TM + 4];
            *(float4*)(br)     = *(const float4*)&Bs[k][tx * TN];
            *(float4*)(br + 4) = *(const float4*)&Bs[k][tx * TN + 4];
#pragma unroll
            for (int i = 0; i < TM; i++)
#pragma unroll
                for (int j = 0; j < TN; j++)
                    acc[i][j] += ar[i] * br[j];
        }
        __syncthreads();
    }

#pragma unroll
    for (int i = 0; i < TM; i++) {
        int r = row0 + ty * TM + i;
        if (r < rows) {
            int   tok = g_tok[e * NTOK + r];
            float w   = g_wt [e * NTOK + r];
            float* orow = out + (size_t)tok * DM + col0 + tx * TN;
#pragma unroll
            for (int j = 0; j < TN; j++) {
                float y = acc[i][j] + bias[col0 + tx * TN + j];
                atomicAdd(&orow[j], w * y);  // exactly 2 adds/elem, commutative
            }
        }
    }
}

// ---------------------------------------------------------------------------
extern "C" void kernel_launch(void* const* d_in, const int* in_sizes, int n_in,
                              void* d_out, int out_size) {
    const float* x  = (const float*)d_in[0];
    const float* gW = (const float*)d_in[1];
    const float* gb = (const float*)d_in[2];
    const float* W1 = (const float*)d_in[3];
    const float* b1 = (const float*)d_in[4];
    const float* W2 = (const float*)d_in[5];
    const float* b2 = (const float*)d_in[6];
    float* out = (float*)d_out;

    int write_topi = (out_size >= NTOK * DM + NTOK * TOPK) ? 1 : 0;

    {
        size_t tot4 = (size_t)NTOK * DM / 4;
        int blocks = (int)((tot4 + 255) / 256);
        zero_kernel<<<blocks, 256>>>(out);
    }
    gating_kernel<<<(NTOK * 32) / 256, 256>>>(x, gW, gb,
                                              out + (size_t)NTOK * DM,
                                              write_topi);
    prefix_kernel<<<1, 1>>>();

    dim3 g1(DFFN / BN, NTOK / BM, NE);
    gemm1_kernel<<<g1, 256>>>(x, W1, b1);

    dim3 g2(DM / BN, NTOK / BM, NE);
    gemm2_kernel<<<g2, 256>>>(W2, b2, out);
}

// round 3
// speedup vs baseline: 2.8930x; 2.8930x over previous
#include <cuda_runtime.h>
#include <cuda_bf16.h>
#include <cstdint>
#include <math.h>

#define NTOK 16384
#define DM   1024
#define DFFN 4096
#define NE   8
#define TOPK 2
#define NSLOT (NTOK * TOPK)

#define BM 128
#define BN 128
#define BK 32
#define STAGES 4
#define THREADS 256

// ---------------- device scratch (static globals: allocation-free) ----------
__device__ int   g_cnt[NE];
__device__ int   g_off[NE];
__device__ int   g_tok[NE * NTOK];
__device__ float g_wt [NE * NTOK];

// padded by BM rows so tile-overhang reads stay in bounds (zero-initialized)
__device__ __align__(16) __nv_bfloat16 XGH[(size_t)(NSLOT + BM) * DM];
__device__ __align__(16) __nv_bfloat16 XGL[(size_t)(NSLOT + BM) * DM];
__device__ __align__(16) __nv_bfloat16 HH [(size_t)(NSLOT + BM) * DFFN];
__device__ __align__(16) __nv_bfloat16 HL [(size_t)(NSLOT + BM) * DFFN];
__device__ __align__(16) __nv_bfloat16 W1H[(size_t)NE * DM * DFFN];
__device__ __align__(16) __nv_bfloat16 W1L[(size_t)NE * DM * DFFN];
__device__ __align__(16) __nv_bfloat16 W2H[(size_t)NE * DFFN * DM];
__device__ __align__(16) __nv_bfloat16 W2L[(size_t)NE * DFFN * DM];

// ---------------- asm helpers ----------------------------------------------
__device__ __forceinline__ void cp16(uint32_t dst, const void* src) {
    asm volatile("cp.async.cg.shared.global [%0], [%1], 16;" :: "r"(dst), "l"(src));
}
#define CP_COMMIT() asm volatile("cp.async.commit_group;" ::: "memory")
#define CP_WAIT(n)  asm volatile("cp.async.wait_group %0;" :: "n"(n) : "memory")

#define LDSM_X4(r0, r1, r2, r3, addr) \
    asm volatile("ldmatrix.sync.aligned.m8n8.x4.shared.b16 {%0,%1,%2,%3}, [%4];" \
                 : "=r"(r0), "=r"(r1), "=r"(r2), "=r"(r3) : "r"(addr))
#define LDSM_X4T(r0, r1, r2, r3, addr) \
    asm volatile("ldmatrix.sync.aligned.m8n8.x4.trans.shared.b16 {%0,%1,%2,%3}, [%4];" \
                 : "=r"(r0), "=r"(r1), "=r"(r2), "=r"(r3) : "r"(addr))

__device__ __forceinline__ void mma_bf16(float* c, const uint32_t* a,
                                         uint32_t b0, uint32_t b1) {
    asm volatile(
        "mma.sync.aligned.m16n8k16.row.col.f32.bf16.bf16.f32 "
        "{%0,%1,%2,%3}, {%4,%5,%6,%7}, {%8,%9}, {%0,%1,%2,%3};"
        : "+f"(c[0]), "+f"(c[1]), "+f"(c[2]), "+f"(c[3])
        : "r"(a[0]), "r"(a[1]), "r"(a[2]), "r"(a[3]), "r"(b0), "r"(b1));
}

// ---------------- smem layout: per stage 32KB ------------------------------
// Ah 128x32 bf16 (8KB), Al (8KB), Bh 32x128 (8KB), Bl (8KB)
#define SA_H(s) ((uint32_t)(s) * 32768u)
#define SA_L(s) ((uint32_t)(s) * 32768u + 8192u)
#define SB_H(s) ((uint32_t)(s) * 32768u + 16384u)
#define SB_L(s) ((uint32_t)(s) * 32768u + 24576u)
#define SMEM_SZ (STAGES * 32768)

// A: row pitch 64B (4x16B chunks), swizzle chunk ^= (row>>1)&3
__device__ __forceinline__ uint32_t a_off(int row, int ch) {
    return (uint32_t)(row * 64 + ((ch ^ ((row >> 1) & 3)) << 4));
}
// B: row pitch 256B (16x16B chunks), swizzle chunk ^= k&7
__device__ __forceinline__ uint32_t b_off(int k, int ch) {
    return (uint32_t)(k * 256 + ((ch ^ (k & 7)) << 4));
}

__device__ __forceinline__ float gelu_f(float v) {
    return 0.5f * v * (1.f + erff(v * 0.70710678118654752440f));
}
__device__ __forceinline__ uint32_t pack_bf16(float a, float b) {
    __nv_bfloat16 x = __float2bfloat16_rn(a), y = __float2bfloat16_rn(b);
    return (uint32_t)__bfloat16_as_ushort(x) | ((uint32_t)__bfloat16_as_ushort(y) << 16);
}

// ---------------- stage loader ----------------------------------------------
__device__ __forceinline__ void load_stage(
    uint32_t sb, int stage,
    const __nv_bfloat16* __restrict__ Ah, const __nv_bfloat16* __restrict__ Al,
    size_t lda, const __nv_bfloat16* __restrict__ Bh,
    const __nv_bfloat16* __restrict__ Bl, size_t ldb,
    size_t arow0, int k0, int n0, int tid) {
#pragma unroll
    for (int i = 0; i < 2; i++) {
        int ca = tid + 256 * i;
        int row = ca >> 2, ch = ca & 3;
        uint32_t off = a_off(row, ch);
        size_t gsrc = (arow0 + row) * lda + k0 + ch * 8;
        cp16(sb + SA_H(stage) + off, Ah + gsrc);
        cp16(sb + SA_L(stage) + off, Al + gsrc);
    }
#pragma unroll
    for (int i = 0; i < 2; i++) {
        int cb = tid + 256 * i;
        int k = cb >> 4, ch = cb & 15;
        uint32_t off = b_off(k, ch);
        size_t gsrc = (size_t)(k0 + k) * ldb + n0 + ch * 8;
        cp16(sb + SB_H(stage) + off, Bh + gsrc);
        cp16(sb + SB_L(stage) + off, Bl + gsrc);
    }
}

// ---------------- per-stage compute: 3-pass bf16 split ----------------------
__device__ __forceinline__ void compute_stage(
    uint32_t sb, int stage, float acc[4][4][4], int wm, int wn, int lane) {
    uint32_t saH = sb + SA_H(stage), saL = sb + SA_L(stage);
    uint32_t sbH = sb + SB_H(stage), sbL = sb + SB_L(stage);
    int l15 = lane & 15, l16 = lane >> 4;
#pragma unroll
    for (int half = 0; half < 2; half++) {     // kk = half*16
        uint32_t ah[4][4], al[4][4], bh[4][2], bl[4][2];
#pragma unroll
        for (int mt = 0; mt < 4; mt++) {
            int row = wm * 64 + mt * 16 + l15;
            int ch = half * 2 + l16;
            uint32_t off = a_off(row, ch);
            LDSM_X4(ah[mt][0], ah[mt][1], ah[mt][2], ah[mt][3], saH + off);
            LDSM_X4(al[mt][0], al[mt][1], al[mt][2], al[mt][3], saL + off);
        }
#pragma unroll
        for (int ng = 0; ng < 2; ng++) {
            int k = half * 16 + l15;
            int ch = wn * 4 + ng * 2 + l16;
            uint32_t off = b_off(k, ch);
            uint32_t t0, t1, t2, t3;
            LDSM_X4T(t0, t1, t2, t3, sbH + off);
            bh[ng * 2][0] = t0; bh[ng * 2][1] = t1;
            bh[ng * 2 + 1][0] = t2; bh[ng * 2 + 1][1] = t3;
            LDSM_X4T(t0, t1, t2, t3, sbL + off);
            bl[ng * 2][0] = t0; bl[ng * 2][1] = t1;
            bl[ng * 2 + 1][0] = t2; bl[ng * 2 + 1][1] = t3;
        }
#pragma unroll
        for (int mt = 0; mt < 4; mt++)
#pragma unroll
            for (int nt = 0; nt < 4; nt++) {
                mma_bf16(acc[mt][nt], ah[mt], bh[nt][0], bh[nt][1]);
                mma_bf16(acc[mt][nt], ah[mt], bl[nt][0], bl[nt][1]);
                mma_bf16(acc[mt][nt], al[mt], bh[nt][0], bh[nt][1]);
            }
    }
}

// ---------------- utility kernels -------------------------------------------
__global__ void zero_kernel(float* __restrict__ out) {
    size_t i = (size_t)blockIdx.x * blockDim.x + threadIdx.x;
    const size_t tot4 = (size_t)NTOK * DM / 4;
    if (i < tot4) ((float4*)out)[i] = make_float4(0.f, 0.f, 0.f, 0.f);
    if (i < NE) g_cnt[i] = 0;
}

__global__ __launch_bounds__(256) void gating_kernel(
    const float* __restrict__ x, const float* __restrict__ gW,
    const float* __restrict__ gb, float* __restrict__ out_topi, int write_topi) {
    int warp = (int)((blockIdx.x * blockDim.x + threadIdx.x) >> 5);
    int lane = threadIdx.x & 31;
    if (warp >= NTOK) return;
    const float* xr = x + (size_t)warp * DM;
    float acc[NE];
#pragma unroll
    for (int e = 0; e < NE; e++) acc[e] = 0.f;
    for (int d = lane; d < DM; d += 32) {
        float xv = xr[d];
        const float4* w4 = (const float4*)(gW + d * NE);
        float4 wa = w4[0], wb = w4[1];
        acc[0] += xv * wa.x; acc[1] += xv * wa.y;
        acc[2] += xv * wa.z; acc[3] += xv * wa.w;
        acc[4] += xv * wb.x; acc[5] += xv * wb.y;
        acc[6] += xv * wb.z; acc[7] += xv * wb.w;
    }
#pragma unroll
    for (int e = 0; e < NE; e++)
#pragma unroll
        for (int o = 16; o > 0; o >>= 1)
            acc[e] += __shfl_xor_sync(0xffffffffu, acc[e], o);
    if (lane == 0) {
        float v0 = -1e30f, v1 = -1e30f; int i0 = 0, i1 = 0;
#pragma unroll
        for (int e = 0; e < NE; e++) {
            float l = acc[e] + gb[e];
            if (l > v0)      { v1 = v0; i1 = i0; v0 = l; i0 = e; }
            else if (l > v1) { v1 = l;  i1 = e; }
        }
        float e1 = expf(v1 - v0);
        float s  = 1.f + e1;
        float w0 = 1.f / s, w1 = e1 / s;
        int p0 = atomicAdd(&g_cnt[i0], 1);
        g_tok[i0 * NTOK + p0] = warp; g_wt[i0 * NTOK + p0] = w0;
        int p1 = atomicAdd(&g_cnt[i1], 1);
        g_tok[i1 * NTOK + p1] = warp; g_wt[i1 * NTOK + p1] = w1;
        if (write_topi) {
            out_topi[warp * 2 + 0] = (float)i0;
            out_topi[warp * 2 + 1] = (float)i1;
        }
    }
}

__global__ void prefix_kernel() {
    int s = 0;
    for (int e = 0; e < NE; e++) { g_off[e] = s; s += g_cnt[e]; }
}

// elementwise fp32 -> bf16 hi/lo split (no transpose needed: ldmatrix.trans)
__global__ __launch_bounds__(256) void split_kernel(
    const float* __restrict__ src, __nv_bfloat16* __restrict__ dh,
    __nv_bfloat16* __restrict__ dl, size_t n4) {
    size_t i = (size_t)blockIdx.x * blockDim.x + threadIdx.x;
    if (i >= n4) return;
    float4 v = ((const float4*)src)[i];
    float h0 = __bfloat162float(__float2bfloat16_rn(v.x));
    float h1 = __bfloat162float(__float2bfloat16_rn(v.y));
    float h2 = __bfloat162float(__float2bfloat16_rn(v.z));
    float h3 = __bfloat162float(__float2bfloat16_rn(v.w));
    uint2 hh, ll;
    hh.x = pack_bf16(v.x, v.y); hh.y = pack_bf16(v.z, v.w);
    ll.x = pack_bf16(v.x - h0, v.y - h1);
    ll.y = pack_bf16(v.z - h2, v.w - h3);
    ((uint2*)dh)[i] = hh;
    ((uint2*)dl)[i] = ll;
}

__global__ __launch_bounds__(256) void gather_split_kernel(const float* __restrict__ x) {
    int e = blockIdx.y;
    int cnt = g_cnt[e], off = g_off[e];
#pragma unroll
    for (int rr = 0; rr < 4; rr++) {
        int r = blockIdx.x * 4 + rr;
        if (r >= cnt) continue;
        int tok = g_tok[e * NTOK + r];
        size_t slot = (size_t)(off + r);
        float4 v = ((const float4*)(x + (size_t)tok * DM))[threadIdx.x];
        float h0 = __bfloat162float(__float2bfloat16_rn(v.x));
        float h1 = __bfloat162float(__float2bfloat16_rn(v.y));
        float h2 = __bfloat162float(__float2bfloat16_rn(v.z));
        float h3 = __bfloat162float(__float2bfloat16_rn(v.w));
        uint2 hh, ll;
        hh.x = pack_bf16(v.x, v.y); hh.y = pack_bf16(v.z, v.w);
        ll.x = pack_bf16(v.x - h0, v.y - h1);
        ll.y = pack_bf16(v.z - h2, v.w - h3);
        ((uint2*)(XGH + slot * DM))[threadIdx.x] = hh;
        ((uint2*)(XGL + slot * DM))[threadIdx.x] = ll;
    }
}

// ---------------- GEMM1: h = split(gelu(xg @ W1 + b1)) ----------------------
__global__ __launch_bounds__(THREADS, 1) void gemm1_mma(const float* __restrict__ b1) {
    extern __shared__ char smem[];
    int e = blockIdx.z;
    int rows = g_cnt[e], off = g_off[e];
    int row0 = blockIdx.y * BM;
    if (row0 >= rows) return;
    int n0 = blockIdx.x * BN;
    uint32_t sb = (uint32_t)__cvta_generic_to_shared(smem);
    int tid = threadIdx.x, lane = tid & 31, wid = tid >> 5;
    int wm = wid & 1, wn = wid >> 1;
    const __nv_bfloat16* Bh = W1H + (size_t)e * DM * DFFN;
    const __nv_bfloat16* Bl = W1L + (size_t)e * DM * DFFN;
    size_t arow0 = (size_t)off + row0;

    float acc[4][4][4];
#pragma unroll
    for (int a = 0; a < 4; a++)
#pragma unroll
        for (int b = 0; b < 4; b++)
#pragma unroll
            for (int c = 0; c < 4; c++) acc[a][b][c] = 0.f;

    const int nk = DM / BK;  // 32
#pragma unroll
    for (int p = 0; p < STAGES - 1; p++) {
        load_stage(sb, p, XGH, XGL, DM, Bh, Bl, DFFN, arow0, p * BK, n0, tid);
        CP_COMMIT();
    }
    for (int t = 0; t < nk; t++) {
        CP_WAIT(STAGES - 2);
        __syncthreads();
        compute_stage(sb, t & (STAGES - 1), acc, wm, wn, lane);
        __syncthreads();
        int nx = t + STAGES - 1;
        if (nx < nk)
            load_stage(sb, nx & (STAGES - 1), XGH, XGL, DM, Bh, Bl, DFFN,
                       arow0, nx * BK, n0, tid);
        CP_COMMIT();
    }

    const float* bias = b1 + (size_t)e * DFFN;
    int quad = lane >> 2, pair = lane & 3;
#pragma unroll
    for (int mt = 0; mt < 4; mt++) {
        int rb = row0 + wm * 64 + mt * 16 + quad;
#pragma unroll
        for (int nt = 0; nt < 4; nt++) {
            int col = n0 + wn * 32 + nt * 8 + pair * 2;
            float bs0 = __ldg(&bias[col]), bs1 = __ldg(&bias[col + 1]);
            if (rb < rows) {
                float g0 = gelu_f(acc[mt][nt][0] + bs0);
                float g1 = gelu_f(acc[mt][nt][1] + bs1);
                float h0 = __bfloat162float(__float2bfloat16_rn(g0));
                float h1 = __bfloat162float(__float2bfloat16_rn(g1));
                size_t o = (size_t)(off + rb) * DFFN + col;
                *(uint32_t*)(HH + o) = pack_bf16(g0, g1);
                *(uint32_t*)(HL + o) = pack_bf16(g0 - h0, g1 - h1);
            }
            if (rb + 8 < rows) {
                float g0 = gelu_f(acc[mt][nt][2] + bs0);
                float g1 = gelu_f(acc[mt][nt][3] + bs1);
                float h0 = __bfloat162float(__float2bfloat16_rn(g0));
                float h1 = __bfloat162float(__float2bfloat16_rn(g1));
                size_t o = (size_t)(off + rb + 8) * DFFN + col;
                *(uint32_t*)(HH + o) = pack_bf16(g0, g1);
                *(uint32_t*)(HL + o) = pack_bf16(g0 - h0, g1 - h1);
            }
        }
    }
}

// ---------------- GEMM2: out[tok] += wt * (h @ W2 + b2) ---------------------
__global__ __launch_bounds__(THREADS, 1) void gemm2_mma(
    const float* __restrict__ b2, float* __restrict__ out) {
    extern __shared__ char smem[];
    int e = blockIdx.z;
    int rows = g_cnt[e], off = g_off[e];
    int row0 = blockIdx.y * BM;
    if (row0 >= rows) return;
    int n0 = blockIdx.x * BN;
    uint32_t sb = (uint32_t)__cvta_generic_to_shared(smem);
    int tid = threadIdx.x, lane = tid & 31, wid = tid >> 5;
    int wm = wid & 1, wn = wid >> 1;
    const __nv_bfloat16* Bh = W2H + (size_t)e * DFFN * DM;
    const __nv_bfloat16* Bl = W2L + (size_t)e * DFFN * DM;
    size_t arow0 = (size_t)off + row0;

    float acc[4][4][4];
#pragma unroll
    for (int a = 0; a < 4; a++)
#pragma unroll
        for (int b = 0; b < 4; b++)
#pragma unroll
            for (int c = 0; c < 4; c++) acc[a][b][c] = 0.f;

    const int nk = DFFN / BK;  // 128
#pragma unroll
    for (int p = 0; p < STAGES - 1; p++) {
        load_stage(sb, p, HH, HL, DFFN, Bh, Bl, DM, arow0, p * BK, n0, tid);
        CP_COMMIT();
    }
    for (int t = 0; t < nk; t++) {
        CP_WAIT(STAGES - 2);
        __syncthreads();
        compute_stage(sb, t & (STAGES - 1), acc, wm, wn, lane);
        __syncthreads();
        int nx = t + STAGES - 1;
        if (nx < nk)
            load_stage(sb, nx & (STAGES - 1), HH, HL, DFFN, Bh, Bl, DM,
                       arow0, nx * BK, n0, tid);
        CP_COMMIT();
    }

    const float* bias = b2 + (size_t)e * DM;
    int quad = lane >> 2, pair = lane & 3;
#pragma unroll
    for (int mt = 0; mt < 4; mt++) {
        int rb = row0 + wm * 64 + mt * 16 + quad;
        int tok0 = 0, tok1 = 0; float wt0 = 0.f, wt1 = 0.f;
        if (rb < rows)     { tok0 = g_tok[e * NTOK + rb];     wt0 = g_wt[e * NTOK + rb]; }
        if (rb + 8 < rows) { tok1 = g_tok[e * NTOK + rb + 8]; wt1 = g_wt[e * NTOK + rb + 8]; }
#pragma unroll
        for (int nt = 0; nt < 4; nt++) {
            int col = n0 + wn * 32 + nt * 8 + pair * 2;
            float bs0 = __ldg(&bias[col]), bs1 = __ldg(&bias[col + 1]);
            if (rb < rows) {
                float* orow = out + (size_t)tok0 * DM + col;
                atomicAdd(&orow[0], (acc[mt][nt][0] + bs0) * wt0);
                atomicAdd(&orow[1], (acc[mt][nt][1] + bs1) * wt0);
            }
            if (rb + 8 < rows) {
                float* orow = out + (size_t)tok1 * DM + col;
                atomicAdd(&orow[0], (acc[mt][nt][2] + bs0) * wt1);
                atomicAdd(&orow[1], (acc[mt][nt][3] + bs1) * wt1);
            }
        }
    }
}

// ---------------- host -------------------------------------------------------
extern "C" void kernel_launch(void* const* d_in, const int* in_sizes, int n_in,
                              void* d_out, int out_size) {
    const float* x  = (const float*)d_in[0];
    const float* gW = (const float*)d_in[1];
    const float* gb = (const float*)d_in[2];
    const float* W1 = (const float*)d_in[3];
    const float* b1 = (const float*)d_in[4];
    const float* W2 = (const float*)d_in[5];
    const float* b2 = (const float*)d_in[6];
    float* out = (float*)d_out;
    int write_topi = (out_size >= NTOK * DM + NTOK * TOPK) ? 1 : 0;

    void *pW1H, *pW1L, *pW2H, *pW2L;
    cudaGetSymbolAddress(&pW1H, W1H); cudaGetSymbolAddress(&pW1L, W1L);
    cudaGetSymbolAddress(&pW2H, W2H); cudaGetSymbolAddress(&pW2L, W2L);

    cudaFuncSetAttribute(gemm1_mma, cudaFuncAttributeMaxDynamicSharedMemorySize, SMEM_SZ);
    cudaFuncSetAttribute(gemm2_mma, cudaFuncAttributeMaxDynamicSharedMemorySize, SMEM_SZ);

    {
        size_t tot4 = (size_t)NTOK * DM / 4;
        zero_kernel<<<(int)((tot4 + 255) / 256), 256>>>(out);
    }
    gating_kernel<<<(NTOK * 32) / 256, 256>>>(x, gW, gb, out + (size_t)NTOK * DM,
                                              write_topi);
    prefix_kernel<<<1, 1>>>();

    {
        size_t n4 = (size_t)NE * DM * DFFN / 4;
        int blocks = (int)((n4 + 255) / 256);
        split_kernel<<<blocks, 256>>>(W1, (__nv_bfloat16*)pW1H, (__nv_bfloat16*)pW1L, n4);
        split_kernel<<<blocks, 256>>>(W2, (__nv_bfloat16*)pW2H, (__nv_bfloat16*)pW2L, n4);
    }
    gather_split_kernel<<<dim3(NTOK / 4, NE), 256>>>(x);

    gemm1_mma<<<dim3(DFFN / BN, NTOK / BM, NE), THREADS, SMEM_SZ>>>(b1);
    gemm2_mma<<<dim3(DM / BN, NTOK / BM, NE), THREADS, SMEM_SZ>>>(b2, out);
}

// round 4
// speedup vs baseline: 3.1217x; 1.0790x over previous
#include <cuda_runtime.h>
#include <cuda_bf16.h>
#include <cstdint>
#include <math.h>

#define NTOK 16384
#define DM   1024
#define DFFN 4096
#define NE   8
#define TOPK 2
#define NSLOT (NTOK * TOPK)

#define BM 128
#define BN 256
#define BK 32
#define STAGES 3
#define THREADS 256

// ---------------- device scratch (static globals: allocation-free) ----------
__device__ int   g_cnt[NE];
__device__ int   g_off[NE];
__device__ int   g_tok[NE * NTOK];
__device__ float g_wt [NE * NTOK];

// padded by BM rows so tile-overhang reads stay in bounds (zero-initialized)
__device__ __align__(16) __nv_bfloat16 XGH[(size_t)(NSLOT + BM) * DM];
__device__ __align__(16) __nv_bfloat16 XGL[(size_t)(NSLOT + BM) * DM];
__device__ __align__(16) __nv_bfloat16 HH [(size_t)(NSLOT + BM) * DFFN];
__device__ __align__(16) __nv_bfloat16 HL [(size_t)(NSLOT + BM) * DFFN];
__device__ __align__(16) __nv_bfloat16 W1H[(size_t)NE * DM * DFFN];
__device__ __align__(16) __nv_bfloat16 W1L[(size_t)NE * DM * DFFN];
__device__ __align__(16) __nv_bfloat16 W2H[(size_t)NE * DFFN * DM];
__device__ __align__(16) __nv_bfloat16 W2L[(size_t)NE * DFFN * DM];

// ---------------- asm helpers ----------------------------------------------
__device__ __forceinline__ void cp16(uint32_t dst, const void* src) {
    asm volatile("cp.async.cg.shared.global [%0], [%1], 16;" :: "r"(dst), "l"(src));
}
#define CP_COMMIT() asm volatile("cp.async.commit_group;" ::: "memory")
#define CP_WAIT(n)  asm volatile("cp.async.wait_group %0;" :: "n"(n) : "memory")

#define LDSM_X4(r0, r1, r2, r3, addr) \
    asm volatile("ldmatrix.sync.aligned.m8n8.x4.shared.b16 {%0,%1,%2,%3}, [%4];" \
                 : "=r"(r0), "=r"(r1), "=r"(r2), "=r"(r3) : "r"(addr))
#define LDSM_X4T(r0, r1, r2, r3, addr) \
    asm volatile("ldmatrix.sync.aligned.m8n8.x4.trans.shared.b16 {%0,%1,%2,%3}, [%4];" \
                 : "=r"(r0), "=r"(r1), "=r"(r2), "=r"(r3) : "r"(addr))

__device__ __forceinline__ void mma_bf16(float* c, const uint32_t* a,
                                         uint32_t b0, uint32_t b1) {
    asm volatile(
        "mma.sync.aligned.m16n8k16.row.col.f32.bf16.bf16.f32 "
        "{%0,%1,%2,%3}, {%4,%5,%6,%7}, {%8,%9}, {%0,%1,%2,%3};"
        : "+f"(c[0]), "+f"(c[1]), "+f"(c[2]), "+f"(c[3])
        : "r"(a[0]), "r"(a[1]), "r"(a[2]), "r"(a[3]), "r"(b0), "r"(b1));
}

// ---------------- smem layout: per stage 48KB ------------------------------
// Ah 128x32 bf16 (8KB), Al (8KB), Bh 32x256 (16KB), Bl (16KB)
#define STAGE_BYTES 49152u
#define SA_H(s) ((uint32_t)(s) * STAGE_BYTES)
#define SA_L(s) ((uint32_t)(s) * STAGE_BYTES + 8192u)
#define SB_H(s) ((uint32_t)(s) * STAGE_BYTES + 16384u)
#define SB_L(s) ((uint32_t)(s) * STAGE_BYTES + 32768u)
#define SMEM_SZ (STAGES * 49152)

// A: row pitch 64B (4x16B chunks), swizzle chunk ^= (row>>1)&3 (conflict-free)
__device__ __forceinline__ uint32_t a_off(int row, int ch) {
    return (uint32_t)(row * 64 + ((ch ^ ((row >> 1) & 3)) << 4));
}
// B: row pitch 512B (32x16B chunks), swizzle low3 of chunk ^= k&7
__device__ __forceinline__ uint32_t b_off(int k, int ch) {
    return (uint32_t)(k * 512 + (((ch & ~7) | ((ch ^ k) & 7)) << 4));
}

__device__ __forceinline__ float gelu_f(float v) {
    return 0.5f * v * (1.f + erff(v * 0.70710678118654752440f));
}
__device__ __forceinline__ uint32_t pack_bf16(float a, float b) {
    __nv_bfloat16 x = __float2bfloat16_rn(a), y = __float2bfloat16_rn(b);
    return (uint32_t)__bfloat16_as_ushort(x) | ((uint32_t)__bfloat16_as_ushort(y) << 16);
}

// ---------------- stage loader ----------------------------------------------
__device__ __forceinline__ void load_stage(
    uint32_t sb, int stage,
    const __nv_bfloat16* __restrict__ Ah, const __nv_bfloat16* __restrict__ Al,
    size_t lda, const __nv_bfloat16* __restrict__ Bh,
    const __nv_bfloat16* __restrict__ Bl, size_t ldb,
    size_t arow0, int k0, int n0, int tid) {
#pragma unroll
    for (int i = 0; i < 2; i++) {           // A: 512 chunks per buffer
        int ca = tid + 256 * i;
        int row = ca >> 2, ch = ca & 3;
        uint32_t off = a_off(row, ch);
        size_t gsrc = (arow0 + row) * lda + k0 + ch * 8;
        cp16(sb + SA_H(stage) + off, Ah + gsrc);
        cp16(sb + SA_L(stage) + off, Al + gsrc);
    }
#pragma unroll
    for (int i = 0; i < 4; i++) {           // B: 1024 chunks per buffer
        int cb = tid + 256 * i;
        int k = cb >> 5, ch = cb & 31;
        uint32_t off = b_off(k, ch);
        size_t gsrc = (size_t)(k0 + k) * ldb + n0 + ch * 8;
        cp16(sb + SB_H(stage) + off, Bh + gsrc);
        cp16(sb + SB_L(stage) + off, Bl + gsrc);
    }
}

// ---------------- per-stage compute: 3-pass bf16 split ----------------------
// warp grid 2x4, warp tile 64x64, acc[4][8][4]
__device__ __forceinline__ void compute_stage(
    uint32_t sb, int stage, float acc[4][8][4], int wm, int wn, int lane) {
    uint32_t saH = sb + SA_H(stage), saL = sb + SA_L(stage);
    uint32_t sbH = sb + SB_H(stage), sbL = sb + SB_L(stage);
    int l15 = lane & 15, l16 = lane >> 4;
#pragma unroll
    for (int half = 0; half < 2; half++) {     // kk = half*16
        uint32_t ah[4][4], al[4][4];
#pragma unroll
        for (int mt = 0; mt < 4; mt++) {
            int row = wm * 64 + mt * 16 + l15;
            int ch = half * 2 + l16;
            uint32_t off = a_off(row, ch);
            LDSM_X4(ah[mt][0], ah[mt][1], ah[mt][2], ah[mt][3], saH + off);
            LDSM_X4(al[mt][0], al[mt][1], al[mt][2], al[mt][3], saL + off);
        }
        uint32_t bf[8][2];
        int kk = half * 16 + l15;
#pragma unroll
        for (int ng = 0; ng < 4; ng++) {
            uint32_t off = b_off(kk, wn * 8 + ng * 2 + l16);
            LDSM_X4T(bf[2 * ng][0], bf[2 * ng][1],
                     bf[2 * ng + 1][0], bf[2 * ng + 1][1], sbH + off);
        }
#pragma unroll
        for (int mt = 0; mt < 4; mt++)
#pragma unroll
            for (int nt = 0; nt < 8; nt++)
                mma_bf16(acc[mt][nt], ah[mt], bf[nt][0], bf[nt][1]);
#pragma unroll
        for (int mt = 0; mt < 4; mt++)
#pragma unroll
            for (int nt = 0; nt < 8; nt++)
                mma_bf16(acc[mt][nt], al[mt], bf[nt][0], bf[nt][1]);
#pragma unroll
        for (int ng = 0; ng < 4; ng++) {
            uint32_t off = b_off(kk, wn * 8 + ng * 2 + l16);
            LDSM_X4T(bf[2 * ng][0], bf[2 * ng][1],
                     bf[2 * ng + 1][0], bf[2 * ng + 1][1], sbL + off);
        }
#pragma unroll
        for (int mt = 0; mt < 4; mt++)
#pragma unroll
            for (int nt = 0; nt < 8; nt++)
                mma_bf16(acc[mt][nt], ah[mt], bf[nt][0], bf[nt][1]);
    }
}

// ---------------- utility kernels -------------------------------------------
__global__ void zero_kernel(float* __restrict__ out) {
    size_t i = (size_t)blockIdx.x * blockDim.x + threadIdx.x;
    const size_t tot4 = (size_t)NTOK * DM / 4;
    if (i < tot4) ((float4*)out)[i] = make_float4(0.f, 0.f, 0.f, 0.f);
    if (i < NE) g_cnt[i] = 0;
}

__global__ __launch_bounds__(256) void gating_kernel(
    const float* __restrict__ x, const float* __restrict__ gW,
    const float* __restrict__ gb, float* __restrict__ out_topi, int write_topi) {
    int warp = (int)((blockIdx.x * blockDim.x + threadIdx.x) >> 5);
    int lane = threadIdx.x & 31;
    if (warp >= NTOK) return;
    const float* xr = x + (size_t)warp * DM;
    float acc[NE];
#pragma unroll
    for (int e = 0; e < NE; e++) acc[e] = 0.f;
    for (int d = lane; d < DM; d += 32) {
        float xv = xr[d];
        const float4* w4 = (const float4*)(gW + d * NE);
        float4 wa = w4[0], wb = w4[1];
        acc[0] += xv * wa.x; acc[1] += xv * wa.y;
        acc[2] += xv * wa.z; acc[3] += xv * wa.w;
        acc[4] += xv * wb.x; acc[5] += xv * wb.y;
        acc[6] += xv * wb.z; acc[7] += xv * wb.w;
    }
#pragma unroll
    for (int e = 0; e < NE; e++)
#pragma unroll
        for (int o = 16; o > 0; o >>= 1)
            acc[e] += __shfl_xor_sync(0xffffffffu, acc[e], o);
    if (lane == 0) {
        float v0 = -1e30f, v1 = -1e30f; int i0 = 0, i1 = 0;
#pragma unroll
        for (int e = 0; e < NE; e++) {
            float l = acc[e] + gb[e];
            if (l > v0)      { v1 = v0; i1 = i0; v0 = l; i0 = e; }
            else if (l > v1) { v1 = l;  i1 = e; }
        }
        float e1 = expf(v1 - v0);
        float s  = 1.f + e1;
        float w0 = 1.f / s, w1 = e1 / s;
        int p0 = atomicAdd(&g_cnt[i0], 1);
        g_tok[i0 * NTOK + p0] = warp; g_wt[i0 * NTOK + p0] = w0;
        int p1 = atomicAdd(&g_cnt[i1], 1);
        g_tok[i1 * NTOK + p1] = warp; g_wt[i1 * NTOK + p1] = w1;
        if (write_topi) {
            out_topi[warp * 2 + 0] = (float)i0;
            out_topi[warp * 2 + 1] = (float)i1;
        }
    }
}

__global__ void prefix_kernel() {
    int s = 0;
    for (int e = 0; e < NE; e++) { g_off[e] = s; s += g_cnt[e]; }
}

// fused elementwise fp32 -> bf16 hi/lo split for BOTH weight tensors
__global__ __launch_bounds__(256) void split_both_kernel(
    const float* __restrict__ W1, const float* __restrict__ W2,
    __nv_bfloat16* __restrict__ w1h, __nv_bfloat16* __restrict__ w1l,
    __nv_bfloat16* __restrict__ w2h, __nv_bfloat16* __restrict__ w2l, size_t n4) {
    size_t i = (size_t)blockIdx.x * blockDim.x + threadIdx.x;
    if (i >= n4) return;
    const float* src = blockIdx.y ? W2 : W1;
    __nv_bfloat16* dh = blockIdx.y ? w2h : w1h;
    __nv_bfloat16* dl = blockIdx.y ? w2l : w1l;
    float4 v = ((const float4*)src)[i];
    float h0 = __bfloat162float(__float2bfloat16_rn(v.x));
    float h1 = __bfloat162float(__float2bfloat16_rn(v.y));
    float h2 = __bfloat162float(__float2bfloat16_rn(v.z));
    float h3 = __bfloat162float(__float2bfloat16_rn(v.w));
    uint2 hh, ll;
    hh.x = pack_bf16(v.x, v.y); hh.y = pack_bf16(v.z, v.w);
    ll.x = pack_bf16(v.x - h0, v.y - h1);
    ll.y = pack_bf16(v.z - h2, v.w - h3);
    ((uint2*)dh)[i] = hh;
    ((uint2*)dl)[i] = ll;
}

__global__ __launch_bounds__(256) void gather_split_kernel(const float* __restrict__ x) {
    int e = blockIdx.y;
    int cnt = g_cnt[e], off = g_off[e];
#pragma unroll
    for (int rr = 0; rr < 4; rr++) {
        int r = blockIdx.x * 4 + rr;
        if (r >= cnt) continue;
        int tok = g_tok[e * NTOK + r];
        size_t slot = (size_t)(off + r);
        float4 v = ((const float4*)(x + (size_t)tok * DM))[threadIdx.x];
        float h0 = __bfloat162float(__float2bfloat16_rn(v.x));
        float h1 = __bfloat162float(__float2bfloat16_rn(v.y));
        float h2 = __bfloat162float(__float2bfloat16_rn(v.z));
        float h3 = __bfloat162float(__float2bfloat16_rn(v.w));
        uint2 hh, ll;
        hh.x = pack_bf16(v.x, v.y); hh.y = pack_bf16(v.z, v.w);
        ll.x = pack_bf16(v.x - h0, v.y - h1);
        ll.y = pack_bf16(v.z - h2, v.w - h3);
        ((uint2*)(XGH + slot * DM))[threadIdx.x] = hh;
        ((uint2*)(XGL + slot * DM))[threadIdx.x] = ll;
    }
}

// ---------------- GEMM1: h = split(gelu(xg @ W1 + b1)) ----------------------
__global__ __launch_bounds__(THREADS, 1) void gemm1_mma(const float* __restrict__ b1) {
    extern __shared__ char smem[];
    int e = blockIdx.z;
    int rows = g_cnt[e], off = g_off[e];
    int row0 = blockIdx.y * BM;
    if (row0 >= rows) return;
    int n0 = blockIdx.x * BN;
    uint32_t sb = (uint32_t)__cvta_generic_to_shared(smem);
    int tid = threadIdx.x, lane = tid & 31, wid = tid >> 5;
    int wm = wid & 1, wn = wid >> 1;
    const __nv_bfloat16* Bh = W1H + (size_t)e * DM * DFFN;
    const __nv_bfloat16* Bl = W1L + (size_t)e * DM * DFFN;
    size_t arow0 = (size_t)off + row0;

    float acc[4][8][4];
#pragma unroll
    for (int a = 0; a < 4; a++)
#pragma unroll
        for (int b = 0; b < 8; b++)
#pragma unroll
            for (int c = 0; c < 4; c++) acc[a][b][c] = 0.f;

    const int nk = DM / BK;  // 32
#pragma unroll
    for (int p = 0; p < STAGES - 1; p++) {
        load_stage(sb, p, XGH, XGL, DM, Bh, Bl, DFFN, arow0, p * BK, n0, tid);
        CP_COMMIT();
    }
    for (int t = 0; t < nk; t++) {
        CP_WAIT(STAGES - 2);
        __syncthreads();
        int nx = t + STAGES - 1;
        if (nx < nk)
            load_stage(sb, nx % STAGES, XGH, XGL, DM, Bh, Bl, DFFN,
                       arow0, nx * BK, n0, tid);
        CP_COMMIT();
        compute_stage(sb, t % STAGES, acc, wm, wn, lane);
    }

    const float* bias = b1 + (size_t)e * DFFN;
    int quad = lane >> 2, pair = lane & 3;
#pragma unroll
    for (int mt = 0; mt < 4; mt++) {
        int rb = row0 + wm * 64 + mt * 16 + quad;
#pragma unroll
        for (int nt = 0; nt < 8; nt++) {
            int col = n0 + wn * 64 + nt * 8 + pair * 2;
            float bs0 = __ldg(&bias[col]), bs1 = __ldg(&bias[col + 1]);
            if (rb < rows) {
                float g0 = gelu_f(acc[mt][nt][0] + bs0);
                float g1 = gelu_f(acc[mt][nt][1] + bs1);
                float h0 = __bfloat162float(__float2bfloat16_rn(g0));
                float h1 = __bfloat162float(__float2bfloat16_rn(g1));
                size_t o = (size_t)(off + rb) * DFFN + col;
                *(uint32_t*)(HH + o) = pack_bf16(g0, g1);
                *(uint32_t*)(HL + o) = pack_bf16(g0 - h0, g1 - h1);
            }
            if (rb + 8 < rows) {
                float g0 = gelu_f(acc[mt][nt][2] + bs0);
                float g1 = gelu_f(acc[mt][nt][3] + bs1);
                float h0 = __bfloat162float(__float2bfloat16_rn(g0));
                float h1 = __bfloat162float(__float2bfloat16_rn(g1));
                size_t o = (size_t)(off + rb + 8) * DFFN + col;
                *(uint32_t*)(HH + o) = pack_bf16(g0, g1);
                *(uint32_t*)(HL + o) = pack_bf16(g0 - h0, g1 - h1);
            }
        }
    }
}

// ---------------- GEMM2: out[tok] += wt * (h @ W2 + b2) ---------------------
__global__ __launch_bounds__(THREADS, 1) void gemm2_mma(
    const float* __restrict__ b2, float* __restrict__ out) {
    extern __shared__ char smem[];
    int e = blockIdx.z;
    int rows = g_cnt[e], off = g_off[e];
    int row0 = blockIdx.y * BM;
    if (row0 >= rows) return;
    int n0 = blockIdx.x * BN;
    uint32_t sb = (uint32_t)__cvta_generic_to_shared(smem);
    int tid = threadIdx.x, lane = tid & 31, wid = tid >> 5;
    int wm = wid & 1, wn = wid >> 1;
    const __nv_bfloat16* Bh = W2H + (size_t)e * DFFN * DM;
    const __nv_bfloat16* Bl = W2L + (size_t)e * DFFN * DM;
    size_t arow0 = (size_t)off + row0;

    float acc[4][8][4];
#pragma unroll
    for (int a = 0; a < 4; a++)
#pragma unroll
        for (int b = 0; b < 8; b++)
#pragma unroll
            for (int c = 0; c < 4; c++) acc[a][b][c] = 0.f;

    const int nk = DFFN / BK;  // 128
#pragma unroll
    for (int p = 0; p < STAGES - 1; p++) {
        load_stage(sb, p, HH, HL, DFFN, Bh, Bl, DM, arow0, p * BK, n0, tid);
        CP_COMMIT();
    }
    for (int t = 0; t < nk; t++) {
        CP_WAIT(STAGES - 2);
        __syncthreads();
        int nx = t + STAGES - 1;
        if (nx < nk)
            load_stage(sb, nx % STAGES, HH, HL, DFFN, Bh, Bl, DM,
                       arow0, nx * BK, n0, tid);
        CP_COMMIT();
        compute_stage(sb, t % STAGES, acc, wm, wn, lane);
    }

    const float* bias = b2 + (size_t)e * DM;
    int quad = lane >> 2, pair = lane & 3;
#pragma unroll
    for (int mt = 0; mt < 4; mt++) {
        int rb = row0 + wm * 64 + mt * 16 + quad;
        int tok0 = 0, tok1 = 0; float wt0 = 0.f, wt1 = 0.f;
        if (rb < rows)     { tok0 = g_tok[e * NTOK + rb];     wt0 = g_wt[e * NTOK + rb]; }
        if (rb + 8 < rows) { tok1 = g_tok[e * NTOK + rb + 8]; wt1 = g_wt[e * NTOK + rb + 8]; }
#pragma unroll
        for (int nt = 0; nt < 8; nt++) {
            int col = n0 + wn * 64 + nt * 8 + pair * 2;
            float bs0 = __ldg(&bias[col]), bs1 = __ldg(&bias[col + 1]);
            if (rb < rows) {
                float* orow = out + (size_t)tok0 * DM + col;
                atomicAdd(&orow[0], (acc[mt][nt][0] + bs0) * wt0);
                atomicAdd(&orow[1], (acc[mt][nt][1] + bs1) * wt0);
            }
            if (rb + 8 < rows) {
                float* orow = out + (size_t)tok1 * DM + col;
                atomicAdd(&orow[0], (acc[mt][nt][2] + bs0) * wt1);
                atomicAdd(&orow[1], (acc[mt][nt][3] + bs1) * wt1);
            }
        }
    }
}

// ---------------- host -------------------------------------------------------
extern "C" void kernel_launch(void* const* d_in, const int* in_sizes, int n_in,
                              void* d_out, int out_size) {
    const float* x  = (const float*)d_in[0];
    const float* gW = (const float*)d_in[1];
    const float* gb = (const float*)d_in[2];
    const float* W1 = (const float*)d_in[3];
    const float* b1 = (const float*)d_in[4];
    const float* W2 = (const float*)d_in[5];
    const float* b2 = (const float*)d_in[6];
    float* out = (float*)d_out;
    int write_topi = (out_size >= NTOK * DM + NTOK * TOPK) ? 1 : 0;

    void *pW1H, *pW1L, *pW2H, *pW2L;
    cudaGetSymbolAddress(&pW1H, W1H); cudaGetSymbolAddress(&pW1L, W1L);
    cudaGetSymbolAddress(&pW2H, W2H); cudaGetSymbolAddress(&pW2L, W2L);

    cudaFuncSetAttribute(gemm1_mma, cudaFuncAttributeMaxDynamicSharedMemorySize, SMEM_SZ);
    cudaFuncSetAttribute(gemm2_mma, cudaFuncAttributeMaxDynamicSharedMemorySize, SMEM_SZ);

    {   // launch 1
        size_t tot4 = (size_t)NTOK * DM / 4;
        zero_kernel<<<(int)((tot4 + 255) / 256), 256>>>(out);
    }
    // launch 2
    gating_kernel<<<(NTOK * 32) / 256, 256>>>(x, gW, gb, out + (size_t)NTOK * DM,
                                              write_topi);
    // launch 3
    prefix_kernel<<<1, 1>>>();
    {   // launch 4 (fused weight splits)
        size_t n4 = (size_t)NE * DM * DFFN / 4;
        split_both_kernel<<<dim3((unsigned)((n4 + 255) / 256), 2), 256>>>(
            W1, W2, (__nv_bfloat16*)pW1H, (__nv_bfloat16*)pW1L,
            (__nv_bfloat16*)pW2H, (__nv_bfloat16*)pW2L, n4);
    }
    // launch 5
    gather_split_kernel<<<dim3(NTOK / 4, NE), 256>>>(x);
    // launch 6  (ncu -s 5 -c 1 captures this one)
    gemm1_mma<<<dim3(DFFN / BN, NTOK / BM, NE), THREADS, SMEM_SZ>>>(b1);
    // launch 7
    gemm2_mma<<<dim3(DM / BN, NTOK / BM, NE), THREADS, SMEM_SZ>>>(b2, out);
}

// round 5
// speedup vs baseline: 4.3778x; 1.4024x over previous
#include <cuda_runtime.h>
#include <cuda_fp16.h>
#include <cstdint>
#include <math.h>

#define NTOK 16384
#define DM   1024
#define DFFN 4096
#define NE   8
#define TOPK 2
#define NSLOT (NTOK * TOPK)

#define BM 128
#define BN 256
#define BK 32
#define STAGES 4
#define THREADS 256

// ---------------- device scratch (static globals: allocation-free) ----------
__device__ int   g_cnt[NE];
__device__ int   g_tok[NE * NTOK];
__device__ float g_wt [NE * NTOK];

// padded by BM rows so tile-overhang reads stay in bounds (never written -> 0)
__device__ __align__(16) __half XGH[(size_t)(NSLOT + BM) * DM];
__device__ __align__(16) __half HH [(size_t)(NSLOT + BM) * DFFN];
__device__ __align__(16) __half W1H[(size_t)NE * DM * DFFN];
__device__ __align__(16) __half W1L[(size_t)NE * DM * DFFN];
__device__ __align__(16) __half W2H[(size_t)NE * DFFN * DM];
__device__ __align__(16) __half W2L[(size_t)NE * DFFN * DM];

// ---------------- asm helpers ----------------------------------------------
__device__ __forceinline__ void cp16(uint32_t dst, const void* src) {
    asm volatile("cp.async.cg.shared.global [%0], [%1], 16;" :: "r"(dst), "l"(src));
}
#define CP_COMMIT() asm volatile("cp.async.commit_group;" ::: "memory")
#define CP_WAIT(n)  asm volatile("cp.async.wait_group %0;" :: "n"(n) : "memory")

#define LDSM_X4(r0, r1, r2, r3, addr) \
    asm volatile("ldmatrix.sync.aligned.m8n8.x4.shared.b16 {%0,%1,%2,%3}, [%4];" \
                 : "=r"(r0), "=r"(r1), "=r"(r2), "=r"(r3) : "r"(addr))
#define LDSM_X4T(r0, r1, r2, r3, addr) \
    asm volatile("ldmatrix.sync.aligned.m8n8.x4.trans.shared.b16 {%0,%1,%2,%3}, [%4];" \
                 : "=r"(r0), "=r"(r1), "=r"(r2), "=r"(r3) : "r"(addr))

__device__ __forceinline__ void mma_f16(float* c, const uint32_t* a,
                                        uint32_t b0, uint32_t b1) {
    asm volatile(
        "mma.sync.aligned.m16n8k16.row.col.f32.f16.f16.f32 "
        "{%0,%1,%2,%3}, {%4,%5,%6,%7}, {%8,%9}, {%0,%1,%2,%3};"
        : "+f"(c[0]), "+f"(c[1]), "+f"(c[2]), "+f"(c[3])
        : "r"(a[0]), "r"(a[1]), "r"(a[2]), "r"(a[3]), "r"(b0), "r"(b1));
}

// ---------------- smem layout: per stage 40KB ------------------------------
// A 128x32 fp16 (8KB), Bh 32x256 (16KB), Bl (16KB)
#define STAGE_BYTES 40960u
#define SA(s)   ((uint32_t)(s) * STAGE_BYTES)
#define SB_H(s) ((uint32_t)(s) * STAGE_BYTES + 8192u)
#define SB_L(s) ((uint32_t)(s) * STAGE_BYTES + 24576u)
#define SMEM_SZ (STAGES * 40960)

// A: row pitch 64B (4x16B chunks), swizzle chunk ^= (row>>1)&3 (conflict-free)
__device__ __forceinline__ uint32_t a_off(int row, int ch) {
    return (uint32_t)(row * 64 + ((ch ^ ((row >> 1) & 3)) << 4));
}
// B: row pitch 512B (32x16B chunks), swizzle low3 of chunk ^= k&7
__device__ __forceinline__ uint32_t b_off(int k, int ch) {
    return (uint32_t)(k * 512 + (((ch & ~7) | ((ch ^ k) & 7)) << 4));
}

__device__ __forceinline__ float gelu_f(float v) {
    return 0.5f * v * (1.f + erff(v * 0.70710678118654752440f));
}
__device__ __forceinline__ uint32_t pack_h2(float a, float b) {
    __half x = __float2half_rn(a), y = __float2half_rn(b);
    return (uint32_t)__half_as_ushort(x) | ((uint32_t)__half_as_ushort(y) << 16);
}
__device__ __forceinline__ int expert_off(int e) {
    int off = 0;
#pragma unroll
    for (int i = 0; i < NE; i++) if (i < e) off += g_cnt[i];
    return off;
}

// ---------------- stage loader ----------------------------------------------
__device__ __forceinline__ void load_stage(
    uint32_t sb, int stage, const __half* __restrict__ A, size_t lda,
    const __half* __restrict__ Bh, const __half* __restrict__ Bl, size_t ldb,
    size_t arow0, int k0, int n0, int tid) {
#pragma unroll
    for (int i = 0; i < 2; i++) {           // A: 512 chunks
        int ca = tid + 256 * i;
        int row = ca >> 2, ch = ca & 3;
        size_t gsrc = (arow0 + row) * lda + k0 + ch * 8;
        cp16(sb + SA(stage) + a_off(row, ch), A + gsrc);
    }
#pragma unroll
    for (int i = 0; i < 4; i++) {           // B: 1024 chunks per buffer
        int cb = tid + 256 * i;
        int k = cb >> 5, ch = cb & 31;
        uint32_t off = b_off(k, ch);
        size_t gsrc = (size_t)(k0 + k) * ldb + n0 + ch * 8;
        cp16(sb + SB_H(stage) + off, Bh + gsrc);
        cp16(sb + SB_L(stage) + off, Bl + gsrc);
    }
}

// ---------------- per-stage compute: 2-pass fp16 split ----------------------
// warp grid 2x4, warp tile 64x64, acc[4][8][4]
__device__ __forceinline__ void compute_stage(
    uint32_t sb, int stage, float acc[4][8][4], int wm, int wn, int lane) {
    uint32_t sa = sb + SA(stage);
    uint32_t sbH = sb + SB_H(stage), sbL = sb + SB_L(stage);
    int l15 = lane & 15, l16 = lane >> 4;
#pragma unroll
    for (int half = 0; half < 2; half++) {     // kk = half*16
        uint32_t ah[4][4];
#pragma unroll
        for (int mt = 0; mt < 4; mt++) {
            int row = wm * 64 + mt * 16 + l15;
            LDSM_X4(ah[mt][0], ah[mt][1], ah[mt][2], ah[mt][3],
                    sa + a_off(row, half * 2 + l16));
        }
        uint32_t bf[8][2];
        int kk = half * 16 + l15;
#pragma unroll
        for (int ng = 0; ng < 4; ng++) {
            uint32_t off = b_off(kk, wn * 8 + ng * 2 + l16);
            LDSM_X4T(bf[2 * ng][0], bf[2 * ng][1],
                     bf[2 * ng + 1][0], bf[2 * ng + 1][1], sbH + off);
        }
#pragma unroll
        for (int mt = 0; mt < 4; mt++)
#pragma unroll
            for (int nt = 0; nt < 8; nt++)
                mma_f16(acc[mt][nt], ah[mt], bf[nt][0], bf[nt][1]);
#pragma unroll
        for (int ng = 0; ng < 4; ng++) {
            uint32_t off = b_off(kk, wn * 8 + ng * 2 + l16);
            LDSM_X4T(bf[2 * ng][0], bf[2 * ng][1],
                     bf[2 * ng + 1][0], bf[2 * ng + 1][1], sbL + off);
        }
#pragma unroll
        for (int mt = 0; mt < 4; mt++)
#pragma unroll
            for (int nt = 0; nt < 8; nt++)
                mma_f16(acc[mt][nt], ah[mt], bf[nt][0], bf[nt][1]);
    }
}

// ---------------- launch 0: zero output + counters ---------------------------
__global__ void zero_kernel(float* __restrict__ out) {
    size_t i = (size_t)blockIdx.x * blockDim.x + threadIdx.x;
    const size_t tot4 = (size_t)NTOK * DM / 4;
    if (i < tot4) ((float4*)out)[i] = make_float4(0.f, 0.f, 0.f, 0.f);
    if (i < NE) g_cnt[i] = 0;
}

// ---------------- launch 1: gating (one warp / token) ------------------------
__global__ __launch_bounds__(256) void gating_kernel(
    const float* __restrict__ x, const float* __restrict__ gW,
    const float* __restrict__ gb, float* __restrict__ out_topi, int write_topi) {
    int warp = (int)((blockIdx.x * blockDim.x + threadIdx.x) >> 5);
    int lane = threadIdx.x & 31;
    if (warp >= NTOK) return;
    const float* xr = x + (size_t)warp * DM;
    float acc[NE];
#pragma unroll
    for (int e = 0; e < NE; e++) acc[e] = 0.f;
    for (int d = lane; d < DM; d += 32) {
        float xv = xr[d];
        const float4* w4 = (const float4*)(gW + d * NE);
        float4 wa = w4[0], wb = w4[1];
        acc[0] += xv * wa.x; acc[1] += xv * wa.y;
        acc[2] += xv * wa.z; acc[3] += xv * wa.w;
        acc[4] += xv * wb.x; acc[5] += xv * wb.y;
        acc[6] += xv * wb.z; acc[7] += xv * wb.w;
    }
#pragma unroll
    for (int e = 0; e < NE; e++)
#pragma unroll
        for (int o = 16; o > 0; o >>= 1)
            acc[e] += __shfl_xor_sync(0xffffffffu, acc[e], o);
    if (lane == 0) {
        float v0 = -1e30f, v1 = -1e30f; int i0 = 0, i1 = 0;
#pragma unroll
        for (int e = 0; e < NE; e++) {
            float l = acc[e] + gb[e];
            if (l > v0)      { v1 = v0; i1 = i0; v0 = l; i0 = e; }
            else if (l > v1) { v1 = l;  i1 = e; }
        }
        float e1 = expf(v1 - v0);
        float s  = 1.f + e1;
        float w0 = 1.f / s, w1 = e1 / s;
        int p0 = atomicAdd(&g_cnt[i0], 1);
        g_tok[i0 * NTOK + p0] = warp; g_wt[i0 * NTOK + p0] = w0;
        int p1 = atomicAdd(&g_cnt[i1], 1);
        g_tok[i1 * NTOK + p1] = warp; g_wt[i1 * NTOK + p1] = w1;
        if (write_topi) {
            out_topi[warp * 2 + 0] = (float)i0;
            out_topi[warp * 2 + 1] = (float)i1;
        }
    }
}

// ---------------- launch 2: fused prep (weight splits + routed gather) -------
__global__ __launch_bounds__(256) void prep_kernel(
    const float* __restrict__ x, const float* __restrict__ W1,
    const float* __restrict__ W2) {
    const size_t n4 = (size_t)NE * DM * DFFN / 4;
    if (blockIdx.y < 2) {                       // weight hi/lo split (fp16)
        size_t i = (size_t)blockIdx.x * blockDim.x + threadIdx.x;
        if (i >= n4) return;
        const float* src = blockIdx.y ? W2 : W1;
        __half* dh = blockIdx.y ? W2H : W1H;
        __half* dl = blockIdx.y ? W2L : W1L;
        float4 v = ((const float4*)src)[i];
        __half a0 = __float2half_rn(v.x), a1 = __float2half_rn(v.y);
        __half a2 = __float2half_rn(v.z), a3 = __float2half_rn(v.w);
        uint2 hh, ll;
        hh.x = (uint32_t)__half_as_ushort(a0) | ((uint32_t)__half_as_ushort(a1) << 16);
        hh.y = (uint32_t)__half_as_ushort(a2) | ((uint32_t)__half_as_ushort(a3) << 16);
        ll.x = pack_h2(v.x - __half2float(a0), v.y - __half2float(a1));
        ll.y = pack_h2(v.z - __half2float(a2), v.w - __half2float(a3));
        ((uint2*)dh)[i] = hh;
        ((uint2*)dl)[i] = ll;
    } else {                                    // gather routed rows -> fp16
        int e = blockIdx.x >> 12;               // 4096 x-blocks per expert
        int cnt = g_cnt[e], off = expert_off(e);
        int rbase = (blockIdx.x & 4095) * 4;
#pragma unroll
        for (int rr = 0; rr < 4; rr++) {
            int r = rbase + rr;
            if (r >= cnt) continue;
            int tok = g_tok[e * NTOK + r];
            float4 v = ((const float4*)(x + (size_t)tok * DM))[threadIdx.x];
            uint2 hh;
            hh.x = pack_h2(v.x, v.y); hh.y = pack_h2(v.z, v.w);
            ((uint2*)(XGH + (size_t)(off + r) * DM))[threadIdx.x] = hh;
        }
    }
}

// ---------------- launch 3: GEMM1  h = fp16(gelu(xg @ W1 + b1)) --------------
__global__ __launch_bounds__(THREADS, 1) void gemm1_mma(const float* __restrict__ b1) {
    extern __shared__ char smem[];
    int e = blockIdx.z;
    int rows = g_cnt[e], off = expert_off(e);
    int row0 = blockIdx.y * BM;
    if (row0 >= rows) return;
    int n0 = blockIdx.x * BN;
    uint32_t sb = (uint32_t)__cvta_generic_to_shared(smem);
    int tid = threadIdx.x, lane = tid & 31, wid = tid >> 5;
    int wm = wid & 1, wn = wid >> 1;
    const __half* Bh = W1H + (size_t)e * DM * DFFN;
    const __half* Bl = W1L + (size_t)e * DM * DFFN;
    size_t arow0 = (size_t)off + row0;

    float acc[4][8][4];
#pragma unroll
    for (int a = 0; a < 4; a++)
#pragma unroll
        for (int b = 0; b < 8; b++)
#pragma unroll
            for (int c = 0; c < 4; c++) acc[a][b][c] = 0.f;

    const int nk = DM / BK;  // 32
#pragma unroll
    for (int p = 0; p < STAGES - 1; p++) {
        load_stage(sb, p, XGH, DM, Bh, Bl, DFFN, arow0, p * BK, n0, tid);
        CP_COMMIT();
    }
    for (int t = 0; t < nk; t++) {
        CP_WAIT(STAGES - 2);
        __syncthreads();
        int nx = t + STAGES - 1;
        if (nx < nk)
            load_stage(sb, nx % STAGES, XGH, DM, Bh, Bl, DFFN,
                       arow0, nx * BK, n0, tid);
        CP_COMMIT();
        compute_stage(sb, t % STAGES, acc, wm, wn, lane);
    }

    const float* bias = b1 + (size_t)e * DFFN;
    int quad = lane >> 2, pair = lane & 3;
#pragma unroll
    for (int mt = 0; mt < 4; mt++) {
        int rb = row0 + wm * 64 + mt * 16 + quad;
#pragma unroll
        for (int nt = 0; nt < 8; nt++) {
            int col = n0 + wn * 64 + nt * 8 + pair * 2;
            float bs0 = __ldg(&bias[col]), bs1 = __ldg(&bias[col + 1]);
            if (rb < rows) {
                size_t o = (size_t)(off + rb) * DFFN + col;
                *(uint32_t*)(HH + o) =
                    pack_h2(gelu_f(acc[mt][nt][0] + bs0), gelu_f(acc[mt][nt][1] + bs1));
            }
            if (rb + 8 < rows) {
                size_t o = (size_t)(off + rb + 8) * DFFN + col;
                *(uint32_t*)(HH + o) =
                    pack_h2(gelu_f(acc[mt][nt][2] + bs0), gelu_f(acc[mt][nt][3] + bs1));
            }
        }
    }
}

// ---------------- launch 4: GEMM2  out[tok] += wt * (h @ W2 + b2) ------------
__global__ __launch_bounds__(THREADS, 1) void gemm2_mma(
    const float* __restrict__ b2, float* __restrict__ out) {
    extern __shared__ char smem[];
    int e = blockIdx.z;
    int rows = g_cnt[e], off = expert_off(e);
    int row0 = blockIdx.y * BM;
    if (row0 >= rows) return;
    int n0 = blockIdx.x * BN;
    uint32_t sb = (uint32_t)__cvta_generic_to_shared(smem);
    int tid = threadIdx.x, lane = tid & 31, wid = tid >> 5;
    int wm = wid & 1, wn = wid >> 1;
    const __half* Bh = W2H + (size_t)e * DFFN * DM;
    const __half* Bl = W2L + (size_t)e * DFFN * DM;
    size_t arow0 = (size_t)off + row0;

    float acc[4][8][4];
#pragma unroll
    for (int a = 0; a < 4; a++)
#pragma unroll
        for (int b = 0; b < 8; b++)
#pragma unroll
            for (int c = 0; c < 4; c++) acc[a][b][c] = 0.f;

    const int nk = DFFN / BK;  // 128
#pragma unroll
    for (int p = 0; p < STAGES - 1; p++) {
        load_stage(sb, p, HH, DFFN, Bh, Bl, DM, arow0, p * BK, n0, tid);
        CP_COMMIT();
    }
    for (int t = 0; t < nk; t++) {
        CP_WAIT(STAGES - 2);
        __syncthreads();
        int nx = t + STAGES - 1;
        if (nx < nk)
            load_stage(sb, nx % STAGES, HH, DFFN, Bh, Bl, DM,
                       arow0, nx * BK, n0, tid);
        CP_COMMIT();
        compute_stage(sb, t % STAGES, acc, wm, wn, lane);
    }

    const float* bias = b2 + (size_t)e * DM;
    int quad = lane >> 2, pair = lane & 3;
#pragma unroll
    for (int mt = 0; mt < 4; mt++) {
        int rb = row0 + wm * 64 + mt * 16 + quad;
        int tok0 = 0, tok1 = 0; float wt0 = 0.f, wt1 = 0.f;
        if (rb < rows)     { tok0 = g_tok[e * NTOK + rb];     wt0 = g_wt[e * NTOK + rb]; }
        if (rb + 8 < rows) { tok1 = g_tok[e * NTOK + rb + 8]; wt1 = g_wt[e * NTOK + rb + 8]; }
#pragma unroll
        for (int nt = 0; nt < 8; nt++) {
            int col = n0 + wn * 64 + nt * 8 + pair * 2;
            float bs0 = __ldg(&bias[col]), bs1 = __ldg(&bias[col + 1]);
            if (rb < rows) {
                float* orow = out + (size_t)tok0 * DM + col;
                atomicAdd(&orow[0], (acc[mt][nt][0] + bs0) * wt0);
                atomicAdd(&orow[1], (acc[mt][nt][1] + bs1) * wt0);
            }
            if (rb + 8 < rows) {
                float* orow = out + (size_t)tok1 * DM + col;
                atomicAdd(&orow[0], (acc[mt][nt][2] + bs0) * wt1);
                atomicAdd(&orow[1], (acc[mt][nt][3] + bs1) * wt1);
            }
        }
    }
}

// ---------------- host -------------------------------------------------------
extern "C" void kernel_launch(void* const* d_in, const int* in_sizes, int n_in,
                              void* d_out, int out_size) {
    const float* x  = (const float*)d_in[0];
    const float* gW = (const float*)d_in[1];
    const float* gb = (const float*)d_in[2];
    const float* W1 = (const float*)d_in[3];
    const float* b1 = (const float*)d_in[4];
    const float* W2 = (const float*)d_in[5];
    const float* b2 = (const float*)d_in[6];
    float* out = (float*)d_out;
    int write_topi = (out_size >= NTOK * DM + NTOK * TOPK) ? 1 : 0;

    cudaFuncSetAttribute(gemm1_mma, cudaFuncAttributeMaxDynamicSharedMemorySize, SMEM_SZ);
    cudaFuncSetAttribute(gemm2_mma, cudaFuncAttributeMaxDynamicSharedMemorySize, SMEM_SZ);

    {   // launch 0
        size_t tot4 = (size_t)NTOK * DM / 4;
        zero_kernel<<<(int)((tot4 + 255) / 256), 256>>>(out);
    }
    // launch 1
    gating_kernel<<<(NTOK * 32) / 256, 256>>>(x, gW, gb, out + (size_t)NTOK * DM,
                                              write_topi);
    // launch 2: fused weight-split (y=0,1) + gather (y=2); prefix inlined
    prep_kernel<<<dim3(32768, 3), 256>>>(x, W1, W2);
    // launch 3 (profiler slot): GEMM1
    gemm1_mma<<<dim3(DFFN / BN, NTOK / BM, NE), THREADS, SMEM_SZ>>>(b1);
    // launch 4: GEMM2
    gemm2_mma<<<dim3(DM / BN, NTOK / BM, NE), THREADS, SMEM_SZ>>>(b2, out);
}